// round 16
// baseline (speedup 1.0000x reference)
#include <cuda_runtime.h>
#include <cuda_fp16.h>

#define NN 100000
#define EE 1600000
#define INDIM 128
#define HID 64
#define TDIM 16
#define NB_SCAN 98   // ceil(NN / 1024)
#define TAB 4096     // time-encoding LUT resolution

// ---- device scratch ----
__device__ __half g_hTh[NN * HID];   // transformed node features (fp16)
__device__ float g_agg[NN * HID];    // normalized aggregation (layer-1 output)
__device__ float g_adst[NN];         // h . attn_w[0:64]
__device__ float g_asrc[NN];         // h . attn_w[64:128]
__device__ int   g_cnt[NN];          // degree counts / scatter cursors
__device__ int   g_off[NN + 1];      // CSR offsets by dst
__device__ int   g_bsum[NB_SCAN];    // scan block sums (raw, never mutated)
__device__ unsigned g_est[EE];       // (src<<15 | t15) sorted by dst
__device__ float g_tab[2][TAB + 1];  // per-layer f(t) = attn_b + sum_k sin(t*tw+tb)*ta

// ---- fused init: time-encoding LUTs (both layers) + zero g_cnt ----
__global__ void init_kernel(const float* __restrict__ t1w, const float* __restrict__ t1b,
                            const float* __restrict__ a1w, const float* __restrict__ a1b,
                            const float* __restrict__ t2w, const float* __restrict__ t2b,
                            const float* __restrict__ a2w, const float* __restrict__ a2b) {
    int i = blockIdx.x * blockDim.x + threadIdx.x;
    if (i < NN) g_cnt[i] = 0;
    if (i < 2 * (TAB + 1)) {
        int layer = i / (TAB + 1);
        int j = i % (TAB + 1);
        float t = (float)j / (float)TAB;
        const float* tw = layer ? t2w : t1w;
        const float* tb = layer ? t2b : t1b;
        const float* aw = layer ? a2w : a1w;
        float f = layer ? a2b[0] : a1b[0];
#pragma unroll
        for (int k = 0; k < TDIM; ++k)
            f += sinf(fmaf(t, tw[k], tb[k])) * aw[2 * HID + k];
        g_tab[layer][j] = f;
    }
}

// ================= preprocessing: bucket edges by dst =================
__global__ void pre_hist_kernel(const int* __restrict__ ei) {
    int e2 = blockIdx.x * blockDim.x + threadIdx.x;   // 2 edges per thread
    if (e2 >= EE / 2) return;
    int2 d = __ldg((const int2*)(ei + EE) + e2);
    atomicAdd(&g_cnt[d.x], 1);
    atomicAdd(&g_cnt[d.y], 1);
}
__global__ void scan_block_kernel() {
    __shared__ int sh[256];
    int t = threadIdx.x;
    int i0 = blockIdx.x * 1024 + t * 4;
    int v0 = (i0 + 0 < NN) ? g_cnt[i0 + 0] : 0;
    int v1 = (i0 + 1 < NN) ? g_cnt[i0 + 1] : 0;
    int v2 = (i0 + 2 < NN) ? g_cnt[i0 + 2] : 0;
    int v3 = (i0 + 3 < NN) ? g_cnt[i0 + 3] : 0;
    int s = v0 + v1 + v2 + v3;
    sh[t] = s;
    __syncthreads();
#pragma unroll
    for (int d = 1; d < 256; d <<= 1) {
        int x = (t >= d) ? sh[t - d] : 0;
        __syncthreads();
        sh[t] += x;
        __syncthreads();
    }
    int run = sh[t] - s;   // exclusive within block
    if (i0 + 0 < NN) g_off[i0 + 0] = run;           run += v0;
    if (i0 + 1 < NN) g_off[i0 + 1] = run;           run += v1;
    if (i0 + 2 < NN) g_off[i0 + 2] = run;           run += v2;
    if (i0 + 3 < NN) g_off[i0 + 3] = run;
    if (t == 255) g_bsum[blockIdx.x] = sh[255];     // raw block sum
}
// scan_add with the top-level scan folded in: every block scans the 98 raw
// block sums in smem (cheap) instead of a dedicated single-block kernel.
__global__ void scan_add_kernel() {
    __shared__ int sh[128];
    int t = threadIdx.x;
    if (t < 128) sh[t] = (t < NB_SCAN) ? g_bsum[t] : 0;
    __syncthreads();
#pragma unroll
    for (int d = 1; d < 128; d <<= 1) {
        int x = (t < 128 && t >= d) ? sh[t - d] : 0;
        __syncthreads();
        if (t < 128) sh[t] += x;
        __syncthreads();
    }
    int i = blockIdx.x * blockDim.x + t;
    if (i < NN) {
        int r = i >> 10;
        g_off[i] += (r > 0) ? sh[r - 1] : 0;   // exclusive top prefix
        g_cnt[i] = 0;                          // reset for scatter cursors
    }
    if (i == 0) g_off[NN] = EE;
}
__global__ void pre_scatter_kernel(const int* __restrict__ ei,
                                   const float* __restrict__ etime) {
    int e2 = blockIdx.x * blockDim.x + threadIdx.x;   // 2 edges per thread
    if (e2 >= EE / 2) return;
    int2 s = __ldg((const int2*)ei + e2);
    int2 d = __ldg((const int2*)(ei + EE) + e2);
    float2 tv = __ldg((const float2*)etime + e2);
    int tq0 = min((int)(__saturatef(tv.x) * 32768.f), 32767);
    int tq1 = min((int)(__saturatef(tv.y) * 32768.f), 32767);
    int p0 = g_off[d.x] + atomicAdd(&g_cnt[d.x], 1);
    g_est[p0] = ((unsigned)s.x << 15) | (unsigned)tq0;
    int p1 = g_off[d.y] + atomicAdd(&g_cnt[d.y], 1);
    g_est[p1] = ((unsigned)s.y << 15) | (unsigned)tq1;
}

__device__ __forceinline__ unsigned packh2(float a, float b) {
    __half2 h = __floats2half2_rn(a, b);
    return *(unsigned*)&h;
}

// ---- tensor-core node transform: hT = act(in) @ W + b ; adst/asrc scalars ----
template <int IN, bool FROM_AGG>
__global__ void transform_mma_kernel(const float* __restrict__ x_in,
                                     const float* __restrict__ W,
                                     const float* __restrict__ bias,
                                     const float* __restrict__ attn_w) {
    constexpr int KS = IN / 16;
    constexpr int XST = IN / 2 + 4;
    __shared__ unsigned xs[64 * XST];
    __shared__ uint2 wf[KS * 8 * 32];

    const int tid = threadIdx.x;
    const int base = blockIdx.x * 64;

    for (int idx = tid; idx < 64 * IN / 4; idx += 128) {
        int row = idx / (IN / 4);
        int c4 = idx % (IN / 4);
        int node = base + row;
        float4 v = make_float4(0.f, 0.f, 0.f, 0.f);
        if (node < NN) {
            if (FROM_AGG) {
                const float4 g = *(const float4*)&g_agg[(size_t)node * IN + c4 * 4];
                v.x = fmaxf(g.x, 0.f); v.y = fmaxf(g.y, 0.f);
                v.z = fmaxf(g.z, 0.f); v.w = fmaxf(g.w, 0.f);
            } else {
                v = *(const float4*)&x_in[(size_t)node * IN + c4 * 4];
            }
        }
        xs[row * XST + c4 * 2]     = packh2(v.x, v.y);
        xs[row * XST + c4 * 2 + 1] = packh2(v.z, v.w);
    }
    for (int idx = tid; idx < KS * 8 * 32; idx += 128) {
        int l  = idx & 31;
        int nt = (idx >> 5) & 7;
        int ks = idx >> 8;
        int k0 = ks * 16 + (l & 3) * 2;
        int n  = nt * 8 + (l >> 2);
        float b00 = __ldg(&W[k0 * HID + n]);
        float b01 = __ldg(&W[(k0 + 1) * HID + n]);
        float b10 = __ldg(&W[(k0 + 8) * HID + n]);
        float b11 = __ldg(&W[(k0 + 9) * HID + n]);
        wf[idx] = make_uint2(packh2(b00, b01), packh2(b10, b11));
    }
    __syncthreads();

    const int warp = tid >> 5;
    const int lane = tid & 31;
    const int q  = lane & 3;
    const int rA = lane >> 2;

    float acc[8][4];
#pragma unroll
    for (int nt = 0; nt < 8; ++nt)
#pragma unroll
        for (int j = 0; j < 4; ++j) acc[nt][j] = 0.f;

    const int rowA = warp * 16 + rA;
#pragma unroll
    for (int ks = 0; ks < KS; ++ks) {
        unsigned a0 = xs[rowA * XST + ks * 8 + q];
        unsigned a1 = xs[(rowA + 8) * XST + ks * 8 + q];
        unsigned a2 = xs[rowA * XST + ks * 8 + q + 4];
        unsigned a3 = xs[(rowA + 8) * XST + ks * 8 + q + 4];
#pragma unroll
        for (int nt = 0; nt < 8; ++nt) {
            uint2 b = wf[(ks * 8 + nt) * 32 + lane];
            asm volatile(
                "mma.sync.aligned.m16n8k16.row.col.f32.f16.f16.f32 "
                "{%0,%1,%2,%3}, {%4,%5,%6,%7}, {%8,%9}, {%0,%1,%2,%3};"
                : "+f"(acc[nt][0]), "+f"(acc[nt][1]),
                  "+f"(acc[nt][2]), "+f"(acc[nt][3])
                : "r"(a0), "r"(a1), "r"(a2), "r"(a3), "r"(b.x), "r"(b.y));
        }
    }

    const int nodeA = base + rowA;
    const int nodeB = nodeA + 8;
    float p1A = 0.f, p2A = 0.f, p1B = 0.f, p2B = 0.f;
#pragma unroll
    for (int nt = 0; nt < 8; ++nt) {
        int n0 = nt * 8 + q * 2;
        float b0 = __ldg(&bias[n0]), b1 = __ldg(&bias[n0 + 1]);
        float h0 = acc[nt][0] + b0, h1 = acc[nt][1] + b1;
        float h2 = acc[nt][2] + b0, h3 = acc[nt][3] + b1;
        if (nodeA < NN) *(unsigned*)&g_hTh[(size_t)nodeA * HID + n0] = packh2(h0, h1);
        if (nodeB < NN) *(unsigned*)&g_hTh[(size_t)nodeB * HID + n0] = packh2(h2, h3);
        float w1a = __ldg(&attn_w[n0]),       w1b = __ldg(&attn_w[n0 + 1]);
        float w2a = __ldg(&attn_w[HID + n0]), w2b = __ldg(&attn_w[HID + n0 + 1]);
        p1A += h0 * w1a + h1 * w1b;  p2A += h0 * w2a + h1 * w2b;
        p1B += h2 * w1a + h3 * w1b;  p2B += h2 * w2a + h3 * w2b;
    }
#pragma unroll
    for (int off = 1; off <= 2; off <<= 1) {
        p1A += __shfl_xor_sync(0xffffffffu, p1A, off);
        p2A += __shfl_xor_sync(0xffffffffu, p2A, off);
        p1B += __shfl_xor_sync(0xffffffffu, p1B, off);
        p2B += __shfl_xor_sync(0xffffffffu, p2B, off);
    }
    if (q == 0) {
        if (nodeA < NN) { g_adst[nodeA] = p1A; g_asrc[nodeA] = p2A; }
        if (nodeB < NN) { g_adst[nodeB] = p1B; g_asrc[nodeB] = p2B; }
    }
}

// ---- segmented aggregation: 16-lane group per dst node, warp-uniform trips ----
template <bool FINAL>
__global__ void seg_agg_kernel(const float* __restrict__ tab,   // g_tab[layer]
                               const float* __restrict__ cls_w, // [64,2] (FINAL)
                               const float* __restrict__ cls_b,
                               float* __restrict__ out) {
    int n = (blockIdx.x * blockDim.x + threadIdx.x) >> 4;   // dst node
    int lane = threadIdx.x & 15;                            // lane in 16-group
    if (n >= NN) return;   // NN*16 % 256 == 0: never splits a warp

    int beg = g_off[n];
    int deg = g_off[n + 1] - beg;
    int maxdeg = max(deg, __shfl_xor_sync(0xffffffffu, deg, 16));
    float adst = __ldg(&g_adst[n]);

    float4 acc = make_float4(0.f, 0.f, 0.f, 0.f);
    float sum_ex = 0.f;

    for (int off = 0; off < maxdeg; off += 16) {
        float ex = 0.f;
        int sr = 0;
        int idx = off + lane;
        if (idx < deg) {
            unsigned p = __ldg(&g_est[beg + idx]);
            sr = (int)(p >> 15);
            int tq = (int)(p & 0x7fffu);
            int i0 = tq >> 3;
            float fr = (float)(tq & 7) * 0.125f;
            float f0 = __ldg(&tab[i0]);
            float f1 = __ldg(&tab[i0 + 1]);
            float tt = fmaf(f1 - f0, fr, f0);
            float a = adst + __ldg(&g_asrc[sr]) + tt;
            a = a > 0.f ? a : 0.01f * a;      // leaky_relu
            ex = __expf(a);                   // softmax shift-invariant
            sum_ex += ex;
        }
        if (maxdeg - off >= 16) {
#pragma unroll
            for (int j = 0; j < 16; ++j) {
                int   sj  = __shfl_sync(0xffffffffu, sr, j, 16);
                float exj = __shfl_sync(0xffffffffu, ex, j, 16);
                uint2 hv = *(const uint2*)&g_hTh[(size_t)sj * HID + lane * 4];
                float2 f01 = __half22float2(*(__half2*)&hv.x);
                float2 f23 = __half22float2(*(__half2*)&hv.y);
                acc.x = fmaf(f01.x, exj, acc.x);
                acc.y = fmaf(f01.y, exj, acc.y);
                acc.z = fmaf(f23.x, exj, acc.z);
                acc.w = fmaf(f23.y, exj, acc.w);
            }
        } else {
            int jmax = maxdeg - off;          // warp-uniform tail
            for (int j = 0; j < jmax; ++j) {
                int   sj  = __shfl_sync(0xffffffffu, sr, j, 16);
                float exj = __shfl_sync(0xffffffffu, ex, j, 16);
                uint2 hv = *(const uint2*)&g_hTh[(size_t)sj * HID + lane * 4];
                float2 f01 = __half22float2(*(__half2*)&hv.x);
                float2 f23 = __half22float2(*(__half2*)&hv.y);
                acc.x = fmaf(f01.x, exj, acc.x);
                acc.y = fmaf(f01.y, exj, acc.y);
                acc.z = fmaf(f23.x, exj, acc.z);
                acc.w = fmaf(f23.y, exj, acc.w);
            }
        }
    }
#pragma unroll
    for (int off = 8; off > 0; off >>= 1)
        sum_ex += __shfl_xor_sync(0xffffffffu, sum_ex, off, 16);
    float coef = 1.f / (sum_ex + 1e-16f);
    acc.x *= coef; acc.y *= coef; acc.z *= coef; acc.w *= coef;

    if (!FINAL) {
        *(float4*)&g_agg[(size_t)n * HID + lane * 4] = acc;
    } else {
        int d0 = lane * 4;
        float o0 = acc.x * __ldg(&cls_w[d0 * 2])     + acc.y * __ldg(&cls_w[(d0 + 1) * 2])
                 + acc.z * __ldg(&cls_w[(d0 + 2) * 2]) + acc.w * __ldg(&cls_w[(d0 + 3) * 2]);
        float o1 = acc.x * __ldg(&cls_w[d0 * 2 + 1])     + acc.y * __ldg(&cls_w[(d0 + 1) * 2 + 1])
                 + acc.z * __ldg(&cls_w[(d0 + 2) * 2 + 1]) + acc.w * __ldg(&cls_w[(d0 + 3) * 2 + 1]);
#pragma unroll
        for (int off = 8; off > 0; off >>= 1) {
            o0 += __shfl_xor_sync(0xffffffffu, o0, off, 16);
            o1 += __shfl_xor_sync(0xffffffffu, o1, off, 16);
        }
        if (lane == 0) {
            out[n * 2 + 0] = o0 + __ldg(&cls_b[0]);
            out[n * 2 + 1] = o1 + __ldg(&cls_b[1]);
        }
    }
}

extern "C" void kernel_launch(void* const* d_in, const int* in_sizes, int n_in,
                              void* d_out, int out_size) {
    const float* x        = (const float*)d_in[0];
    const int*   ei       = (const int*)  d_in[1];
    const float* etime    = (const float*)d_in[2];
    const float* lin1_w   = (const float*)d_in[3];
    const float* lin1_b   = (const float*)d_in[4];
    const float* attn1_w  = (const float*)d_in[5];
    const float* attn1_b  = (const float*)d_in[6];
    const float* t1_w     = (const float*)d_in[7];
    const float* t1_b     = (const float*)d_in[8];
    const float* lin2_w   = (const float*)d_in[9];
    const float* lin2_b   = (const float*)d_in[10];
    const float* attn2_w  = (const float*)d_in[11];
    const float* attn2_b  = (const float*)d_in[12];
    const float* t2_w     = (const float*)d_in[13];
    const float* t2_b     = (const float*)d_in[14];
    const float* cls_w    = (const float*)d_in[15];
    const float* cls_b    = (const float*)d_in[16];
    float* out = (float*)d_out;

    float* tabp; cudaGetSymbolAddress((void**)&tabp, g_tab);

    const int NBn = (NN + 255) / 256;             // covers NN and 2*(TAB+1)
    const int NB2 = (EE / 2 + 255) / 256;
    const int TB  = (NN + 63) / 64;
    const int SB  = (NN * 16 + 255) / 256;

    // ---- init (LUTs + cnt zero), then CSR-by-dst ----
    init_kernel<<<NBn, 256>>>(t1_w, t1_b, attn1_w, attn1_b,
                              t2_w, t2_b, attn2_w, attn2_b);
    pre_hist_kernel<<<NB2, 256>>>(ei);
    scan_block_kernel<<<NB_SCAN, 256>>>();
    scan_add_kernel<<<NBn, 256>>>();
    pre_scatter_kernel<<<NB2, 256>>>(ei, etime);

    // ---- layer 1 ----
    transform_mma_kernel<INDIM, false><<<TB, 128>>>(x, lin1_w, lin1_b, attn1_w);
    seg_agg_kernel<false><<<SB, 256>>>(tabp, nullptr, nullptr, nullptr);

    // ---- layer 2 (input = relu(agg)) + fused classifier ----
    transform_mma_kernel<HID, true><<<TB, 128>>>(nullptr, lin2_w, lin2_b, attn2_w);
    seg_agg_kernel<true><<<SB, 256>>>(tabp + (TAB + 1), cls_w, cls_b, out);
}

// round 17
// speedup vs baseline: 1.3840x; 1.3840x over previous
#include <cuda_runtime.h>
#include <cuda_fp16.h>

#define NN 100000
#define EE 1600000
#define INDIM 128
#define HID 64
#define TDIM 16
#define NB_SCAN 98   // ceil(NN / 1024)
#define TAB 4096     // time-encoding LUT resolution

// ---- device scratch ----
__device__ __half g_hTh[NN * HID];  // transformed node features (fp16)
__device__ float g_agg[NN * HID];   // normalized aggregation (layer-1 output)
__device__ float g_adst[NN];        // h . attn_w[0:64]
__device__ float g_asrc[NN];        // h . attn_w[64:128]
__device__ int   g_cnt[NN];         // degree counts / scatter cursors
__device__ int   g_off[NN + 1];     // CSR offsets by dst
__device__ int   g_bsum[NB_SCAN];   // scan block sums (raw, never mutated)
__device__ int2  g_est[EE];         // (src, time-bits) sorted by dst
__device__ float g_tab[2][TAB + 1]; // per-layer f(t) = attn_b + sum_k sin(t*tw+tb)*ta

// ---- fused init: time-encoding LUTs (both layers) + zero g_cnt ----
__global__ void init_kernel(const float* __restrict__ t1w, const float* __restrict__ t1b,
                            const float* __restrict__ a1w, const float* __restrict__ a1b,
                            const float* __restrict__ t2w, const float* __restrict__ t2b,
                            const float* __restrict__ a2w, const float* __restrict__ a2b) {
    int i = blockIdx.x * blockDim.x + threadIdx.x;
    if (i < NN) g_cnt[i] = 0;
    if (i < 2 * (TAB + 1)) {
        int layer = i / (TAB + 1);
        int j = i % (TAB + 1);
        float t = (float)j / (float)TAB;
        const float* tw = layer ? t2w : t1w;
        const float* tb = layer ? t2b : t1b;
        const float* aw = layer ? a2w : a1w;
        float f = layer ? a2b[0] : a1b[0];
#pragma unroll
        for (int k = 0; k < TDIM; ++k)
            f += sinf(fmaf(t, tw[k], tb[k])) * aw[2 * HID + k];
        g_tab[layer][j] = f;
    }
}

// ================= preprocessing: bucket edges by dst =================
__global__ void pre_hist_kernel(const int* __restrict__ ei) {
    int e = blockIdx.x * blockDim.x + threadIdx.x;
    if (e < EE) atomicAdd(&g_cnt[__ldg(&ei[EE + e])], 1);
}
__global__ void scan_block_kernel() {
    __shared__ int sh[256];
    int t = threadIdx.x;
    int i0 = blockIdx.x * 1024 + t * 4;
    int v0 = (i0 + 0 < NN) ? g_cnt[i0 + 0] : 0;
    int v1 = (i0 + 1 < NN) ? g_cnt[i0 + 1] : 0;
    int v2 = (i0 + 2 < NN) ? g_cnt[i0 + 2] : 0;
    int v3 = (i0 + 3 < NN) ? g_cnt[i0 + 3] : 0;
    int s = v0 + v1 + v2 + v3;
    sh[t] = s;
    __syncthreads();
#pragma unroll
    for (int d = 1; d < 256; d <<= 1) {
        int x = (t >= d) ? sh[t - d] : 0;
        __syncthreads();
        sh[t] += x;
        __syncthreads();
    }
    int run = sh[t] - s;   // exclusive within block
    if (i0 + 0 < NN) g_off[i0 + 0] = run;           run += v0;
    if (i0 + 1 < NN) g_off[i0 + 1] = run;           run += v1;
    if (i0 + 2 < NN) g_off[i0 + 2] = run;           run += v2;
    if (i0 + 3 < NN) g_off[i0 + 3] = run;
    if (t == 255) g_bsum[blockIdx.x] = sh[255];     // raw block sum
}
// scan_add with the top-level scan folded in: every block scans the 98 raw
// block sums in smem (~200 cycles) instead of a dedicated 4.3us kernel.
__global__ void scan_add_kernel() {
    __shared__ int sh[128];
    int t = threadIdx.x;
    if (t < 128) sh[t] = (t < NB_SCAN) ? g_bsum[t] : 0;
    __syncthreads();
#pragma unroll
    for (int d = 1; d < 128; d <<= 1) {
        int x = (t < 128 && t >= d) ? sh[t - d] : 0;
        __syncthreads();
        if (t < 128) sh[t] += x;
        __syncthreads();
    }
    int i = blockIdx.x * blockDim.x + t;
    if (i < NN) {
        int r = i >> 10;
        g_off[i] += (r > 0) ? sh[r - 1] : 0;   // exclusive top prefix
        g_cnt[i] = 0;                          // reset for scatter cursors
    }
    if (i == 0) g_off[NN] = EE;
}
__global__ void pre_scatter_kernel(const int* __restrict__ ei,
                                   const float* __restrict__ etime) {
    int e = blockIdx.x * blockDim.x + threadIdx.x;
    if (e >= EE) return;
    int dst = __ldg(&ei[EE + e]);
    int pos = g_off[dst] + atomicAdd(&g_cnt[dst], 1);
    g_est[pos] = make_int2(__ldg(&ei[e]), __float_as_int(__ldg(&etime[e])));
}

__device__ __forceinline__ unsigned packh2(float a, float b) {
    __half2 h = __floats2half2_rn(a, b);
    return *(unsigned*)&h;
}

// ---- tensor-core node transform: hT = act(in) @ W + b ; adst/asrc scalars ----
template <int IN, bool FROM_AGG>
__global__ void transform_mma_kernel(const float* __restrict__ x_in,
                                     const float* __restrict__ W,
                                     const float* __restrict__ bias,
                                     const float* __restrict__ attn_w) {
    constexpr int KS = IN / 16;
    constexpr int XST = IN / 2 + 4;
    __shared__ unsigned xs[64 * XST];
    __shared__ uint2 wf[KS * 8 * 32];

    const int tid = threadIdx.x;
    const int base = blockIdx.x * 64;

    for (int idx = tid; idx < 64 * IN / 4; idx += 128) {
        int row = idx / (IN / 4);
        int c4 = idx % (IN / 4);
        int node = base + row;
        float4 v = make_float4(0.f, 0.f, 0.f, 0.f);
        if (node < NN) {
            if (FROM_AGG) {
                const float4 g = *(const float4*)&g_agg[(size_t)node * IN + c4 * 4];
                v.x = fmaxf(g.x, 0.f); v.y = fmaxf(g.y, 0.f);
                v.z = fmaxf(g.z, 0.f); v.w = fmaxf(g.w, 0.f);
            } else {
                v = *(const float4*)&x_in[(size_t)node * IN + c4 * 4];
            }
        }
        xs[row * XST + c4 * 2]     = packh2(v.x, v.y);
        xs[row * XST + c4 * 2 + 1] = packh2(v.z, v.w);
    }
    for (int idx = tid; idx < KS * 8 * 32; idx += 128) {
        int l  = idx & 31;
        int nt = (idx >> 5) & 7;
        int ks = idx >> 8;
        int k0 = ks * 16 + (l & 3) * 2;
        int n  = nt * 8 + (l >> 2);
        float b00 = __ldg(&W[k0 * HID + n]);
        float b01 = __ldg(&W[(k0 + 1) * HID + n]);
        float b10 = __ldg(&W[(k0 + 8) * HID + n]);
        float b11 = __ldg(&W[(k0 + 9) * HID + n]);
        wf[idx] = make_uint2(packh2(b00, b01), packh2(b10, b11));
    }
    __syncthreads();

    const int warp = tid >> 5;
    const int lane = tid & 31;
    const int q  = lane & 3;
    const int rA = lane >> 2;

    float acc[8][4];
#pragma unroll
    for (int nt = 0; nt < 8; ++nt)
#pragma unroll
        for (int j = 0; j < 4; ++j) acc[nt][j] = 0.f;

    const int rowA = warp * 16 + rA;
#pragma unroll
    for (int ks = 0; ks < KS; ++ks) {
        unsigned a0 = xs[rowA * XST + ks * 8 + q];
        unsigned a1 = xs[(rowA + 8) * XST + ks * 8 + q];
        unsigned a2 = xs[rowA * XST + ks * 8 + q + 4];
        unsigned a3 = xs[(rowA + 8) * XST + ks * 8 + q + 4];
#pragma unroll
        for (int nt = 0; nt < 8; ++nt) {
            uint2 b = wf[(ks * 8 + nt) * 32 + lane];
            asm volatile(
                "mma.sync.aligned.m16n8k16.row.col.f32.f16.f16.f32 "
                "{%0,%1,%2,%3}, {%4,%5,%6,%7}, {%8,%9}, {%0,%1,%2,%3};"
                : "+f"(acc[nt][0]), "+f"(acc[nt][1]),
                  "+f"(acc[nt][2]), "+f"(acc[nt][3])
                : "r"(a0), "r"(a1), "r"(a2), "r"(a3), "r"(b.x), "r"(b.y));
        }
    }

    const int nodeA = base + rowA;
    const int nodeB = nodeA + 8;
    float p1A = 0.f, p2A = 0.f, p1B = 0.f, p2B = 0.f;
#pragma unroll
    for (int nt = 0; nt < 8; ++nt) {
        int n0 = nt * 8 + q * 2;
        float b0 = __ldg(&bias[n0]), b1 = __ldg(&bias[n0 + 1]);
        float h0 = acc[nt][0] + b0, h1 = acc[nt][1] + b1;
        float h2 = acc[nt][2] + b0, h3 = acc[nt][3] + b1;
        if (nodeA < NN) *(unsigned*)&g_hTh[(size_t)nodeA * HID + n0] = packh2(h0, h1);
        if (nodeB < NN) *(unsigned*)&g_hTh[(size_t)nodeB * HID + n0] = packh2(h2, h3);
        float w1a = __ldg(&attn_w[n0]),       w1b = __ldg(&attn_w[n0 + 1]);
        float w2a = __ldg(&attn_w[HID + n0]), w2b = __ldg(&attn_w[HID + n0 + 1]);
        p1A += h0 * w1a + h1 * w1b;  p2A += h0 * w2a + h1 * w2b;
        p1B += h2 * w1a + h3 * w1b;  p2B += h2 * w2a + h3 * w2b;
    }
#pragma unroll
    for (int off = 1; off <= 2; off <<= 1) {
        p1A += __shfl_xor_sync(0xffffffffu, p1A, off);
        p2A += __shfl_xor_sync(0xffffffffu, p2A, off);
        p1B += __shfl_xor_sync(0xffffffffu, p1B, off);
        p2B += __shfl_xor_sync(0xffffffffu, p2B, off);
    }
    if (q == 0) {
        if (nodeA < NN) { g_adst[nodeA] = p1A; g_asrc[nodeA] = p2A; }
        if (nodeB < NN) { g_adst[nodeB] = p1B; g_asrc[nodeB] = p2B; }
    }
}

// ---- segmented aggregation: 16-lane group per dst node, warp-uniform trips ----
// Full chunks use a compile-time-unrolled 16-deep broadcast loop.
template <bool FINAL>
__global__ void seg_agg_kernel(const float* __restrict__ tab,   // g_tab[layer]
                               const float* __restrict__ cls_w, // [64,2] (FINAL)
                               const float* __restrict__ cls_b,
                               float* __restrict__ out) {
    int n = (blockIdx.x * blockDim.x + threadIdx.x) >> 4;   // dst node
    int lane = threadIdx.x & 15;                            // lane in 16-group
    if (n >= NN) return;   // NN*16 % 256 == 0: never splits a warp

    int beg = g_off[n];
    int deg = g_off[n + 1] - beg;
    int maxdeg = max(deg, __shfl_xor_sync(0xffffffffu, deg, 16));
    float adst = __ldg(&g_adst[n]);

    float4 acc = make_float4(0.f, 0.f, 0.f, 0.f);
    float sum_ex = 0.f;

    for (int off = 0; off < maxdeg; off += 16) {
        float ex = 0.f;
        int sr = 0;
        int idx = off + lane;
        if (idx < deg) {
            int2 et = __ldg(&g_est[beg + idx]);
            sr = et.x;
            float tv = __int_as_float(et.y);
            float u = __saturatef(tv) * (float)TAB;
            int i0 = min((int)u, TAB - 1);
            float fr = u - (float)i0;
            float f0 = __ldg(&tab[i0]);
            float f1 = __ldg(&tab[i0 + 1]);
            float tt = fmaf(f1 - f0, fr, f0);
            float a = adst + __ldg(&g_asrc[sr]) + tt;
            a = a > 0.f ? a : 0.01f * a;      // leaky_relu
            ex = __expf(a);                   // softmax shift-invariant
            sum_ex += ex;
        }
        if (maxdeg - off >= 16) {
#pragma unroll
            for (int j = 0; j < 16; ++j) {
                int   sj  = __shfl_sync(0xffffffffu, sr, j, 16);
                float exj = __shfl_sync(0xffffffffu, ex, j, 16);
                uint2 hv = *(const uint2*)&g_hTh[(size_t)sj * HID + lane * 4];
                float2 f01 = __half22float2(*(__half2*)&hv.x);
                float2 f23 = __half22float2(*(__half2*)&hv.y);
                acc.x = fmaf(f01.x, exj, acc.x);
                acc.y = fmaf(f01.y, exj, acc.y);
                acc.z = fmaf(f23.x, exj, acc.z);
                acc.w = fmaf(f23.y, exj, acc.w);
            }
        } else {
            int jmax = maxdeg - off;          // warp-uniform tail
            for (int j = 0; j < jmax; ++j) {
                int   sj  = __shfl_sync(0xffffffffu, sr, j, 16);
                float exj = __shfl_sync(0xffffffffu, ex, j, 16);
                uint2 hv = *(const uint2*)&g_hTh[(size_t)sj * HID + lane * 4];
                float2 f01 = __half22float2(*(__half2*)&hv.x);
                float2 f23 = __half22float2(*(__half2*)&hv.y);
                acc.x = fmaf(f01.x, exj, acc.x);
                acc.y = fmaf(f01.y, exj, acc.y);
                acc.z = fmaf(f23.x, exj, acc.z);
                acc.w = fmaf(f23.y, exj, acc.w);
            }
        }
    }
#pragma unroll
    for (int off = 8; off > 0; off >>= 1)
        sum_ex += __shfl_xor_sync(0xffffffffu, sum_ex, off, 16);
    float coef = 1.f / (sum_ex + 1e-16f);
    acc.x *= coef; acc.y *= coef; acc.z *= coef; acc.w *= coef;

    if (!FINAL) {
        *(float4*)&g_agg[(size_t)n * HID + lane * 4] = acc;
    } else {
        int d0 = lane * 4;
        float o0 = acc.x * __ldg(&cls_w[d0 * 2])     + acc.y * __ldg(&cls_w[(d0 + 1) * 2])
                 + acc.z * __ldg(&cls_w[(d0 + 2) * 2]) + acc.w * __ldg(&cls_w[(d0 + 3) * 2]);
        float o1 = acc.x * __ldg(&cls_w[d0 * 2 + 1])     + acc.y * __ldg(&cls_w[(d0 + 1) * 2 + 1])
                 + acc.z * __ldg(&cls_w[(d0 + 2) * 2 + 1]) + acc.w * __ldg(&cls_w[(d0 + 3) * 2 + 1]);
#pragma unroll
        for (int off = 8; off > 0; off >>= 1) {
            o0 += __shfl_xor_sync(0xffffffffu, o0, off, 16);
            o1 += __shfl_xor_sync(0xffffffffu, o1, off, 16);
        }
        if (lane == 0) {
            out[n * 2 + 0] = o0 + __ldg(&cls_b[0]);
            out[n * 2 + 1] = o1 + __ldg(&cls_b[1]);
        }
    }
}

extern "C" void kernel_launch(void* const* d_in, const int* in_sizes, int n_in,
                              void* d_out, int out_size) {
    const float* x        = (const float*)d_in[0];
    const int*   ei       = (const int*)  d_in[1];
    const float* etime    = (const float*)d_in[2];
    const float* lin1_w   = (const float*)d_in[3];
    const float* lin1_b   = (const float*)d_in[4];
    const float* attn1_w  = (const float*)d_in[5];
    const float* attn1_b  = (const float*)d_in[6];
    const float* t1_w     = (const float*)d_in[7];
    const float* t1_b     = (const float*)d_in[8];
    const float* lin2_w   = (const float*)d_in[9];
    const float* lin2_b   = (const float*)d_in[10];
    const float* attn2_w  = (const float*)d_in[11];
    const float* attn2_b  = (const float*)d_in[12];
    const float* t2_w     = (const float*)d_in[13];
    const float* t2_b     = (const float*)d_in[14];
    const float* cls_w    = (const float*)d_in[15];
    const float* cls_b    = (const float*)d_in[16];
    float* out = (float*)d_out;

    float* tabp; cudaGetSymbolAddress((void**)&tabp, g_tab);

    const int NBn = (NN + 255) / 256;             // covers NN and 2*(TAB+1)
    const int NBe = (EE + 255) / 256;
    const int TB  = (NN + 63) / 64;
    const int SB  = (NN * 16 + 255) / 256;

    // ---- init (LUTs + cnt zero), then CSR-by-dst (R14 data path) ----
    init_kernel<<<NBn, 256>>>(t1_w, t1_b, attn1_w, attn1_b,
                              t2_w, t2_b, attn2_w, attn2_b);
    pre_hist_kernel<<<NBe, 256>>>(ei);
    scan_block_kernel<<<NB_SCAN, 256>>>();
    scan_add_kernel<<<NBn, 256>>>();
    pre_scatter_kernel<<<NBe, 256>>>(ei, etime);

    // ---- layer 1 ----
    transform_mma_kernel<INDIM, false><<<TB, 128>>>(x, lin1_w, lin1_b, attn1_w);
    seg_agg_kernel<false><<<SB, 256>>>(tabp, nullptr, nullptr, nullptr);

    // ---- layer 2 (input = relu(agg)) + fused classifier ----
    transform_mma_kernel<HID, true><<<TB, 128>>>(nullptr, lin2_w, lin2_b, attn2_w);
    seg_agg_kernel<true><<<SB, 256>>>(tabp + (TAB + 1), cls_w, cls_b, out);
}